// round 3
// baseline (speedup 1.0000x reference)
#include <cuda_runtime.h>
#include <cuda_bf16.h>

// Problem constants (fixed shapes per problem definition)
#define MAX_M 600000          // corners
#define EPSF 1e-8f
#define WSCALE 0.99f

// Scratch (no cudaMalloc allowed)
__device__ int   g_winner[MAX_M];        // last flat-index writer per corner slot
__device__ float g_world [MAX_M * 3];    // world-space corner positions

// ---------------------------------------------------------------------------
// Kernel 0: init winners to -1 (every launch; graph-replayable)
// ---------------------------------------------------------------------------
__global__ void k_init(int M) {
    int j = blockIdx.x * blockDim.x + threadIdx.x;
    if (j < M) g_winner[j] = -1;
}

// ---------------------------------------------------------------------------
// Kernel 1: winner = max flat index writing each slot (== JAX sequential
// last-write-wins semantics for .at[].set with duplicate indices).
// cube_idx arrives as int32 (harness dtype set is f32/i32/bf16 only).
// ---------------------------------------------------------------------------
__global__ void k_scatter(const int* __restrict__ cube_idx, int total, int M) {
    int k = blockIdx.x * blockDim.x + threadIdx.x;
    if (k >= total) return;
    int j = cube_idx[k];
    if (j < 0) j = 0;
    if (j >= M) j = M - 1;     // defensive: never fault on a dtype surprise
    atomicMax(&g_winner[j], k);
}

// ---------------------------------------------------------------------------
// Kernel 2: world = unique_pos * (2/res) - 1 + deform
// unique_pos[j] = voxel_coords[winner/8] + CUBE_CORNERS[winner&7] (or 0).
// ---------------------------------------------------------------------------
__global__ void k_world(const int* __restrict__ vox,
                        const float* __restrict__ deform,
                        int M, float scale) {
    int j = blockIdx.x * blockDim.x + threadIdx.x;
    if (j >= M) return;
    int k = g_winner[j];
    float px = 0.f, py = 0.f, pz = 0.f;
    if (k >= 0) {
        int i = k >> 3, c = k & 7;
        px = (float)vox[i * 3 + 0] + (float)(c & 1);
        py = (float)vox[i * 3 + 1] + (float)((c >> 1) & 1);
        pz = (float)vox[i * 3 + 2] + (float)((c >> 2) & 1);
    }
    g_world[j * 3 + 0] = px * scale - 1.f + deform[j * 3 + 0];
    g_world[j * 3 + 1] = py * scale - 1.f + deform[j * 3 + 1];
    g_world[j * 3 + 2] = pz * scale - 1.f + deform[j * 3 + 2];
}

// ---------------------------------------------------------------------------
// Kernel 3: per-cube dual-contouring math. One thread per cube.
// Outputs (flat concat, float32): [vertices 3N][L_dev 12N][p_alpha 3N][n_out 3N]
// (faces is an empty (0,3) array -> contributes nothing)
// ---------------------------------------------------------------------------
__global__ void __launch_bounds__(256)
k_main(const int* __restrict__ cube_idx,
       const float* __restrict__ sdf,
       const float* __restrict__ alpha,
       const float* __restrict__ beta,
       float* __restrict__ out, int N) {
    int i = blockIdx.x * blockDim.x + threadIdx.x;
    if (i >= N) return;

    // --- corner indices (coalesced int4 loads) ---
    const int4* cp = (const int4*)(cube_idx + (size_t)i * 8);
    int4 ca = cp[0], cb = cp[1];
    int ci[8] = {ca.x, ca.y, ca.z, ca.w, cb.x, cb.y, cb.z, cb.w};

    float s[8], wx[8], wy[8], wz[8];
    bool anyp = false, anyn = false;
#pragma unroll
    for (int c = 0; c < 8; c++) {
        int j = ci[c];
        float sv = sdf[j];
        s[c] = sv;
        anyp |= (sv > 0.f);
        anyn |= !(sv > 0.f);
        wx[c] = g_world[j * 3 + 0];
        wy[c] = g_world[j * 3 + 1];
        wz[c] = g_world[j * 3 + 2];
    }
    bool surf = anyp && anyn;

    // --- normalized weights ---
    const float4* ap = (const float4*)(alpha + (size_t)i * 8);
    float4 av0 = ap[0], av1 = ap[1];
    float aarr[8] = {av0.x, av0.y, av0.z, av0.w, av1.x, av1.y, av1.z, av1.w};
    float an[8];
#pragma unroll
    for (int c = 0; c < 8; c++) an[c] = tanhf(aarr[c]) * WSCALE + 1.f;

    float bn[12];
#pragma unroll
    for (int e = 0; e < 12; e++) bn[e] = tanhf(beta[(size_t)i * 12 + e]) * WSCALE + 1.f;

    const int E0[12] = {0, 1, 4, 0, 2, 3, 6, 2, 2, 3, 7, 6};
    const int E1[12] = {1, 5, 5, 4, 3, 7, 7, 6, 0, 1, 5, 4};

    // --- pass A: accumulate vd, n_alpha numerators ---
    float wbe[12];
    float wsum = 0.f;
    float vdx = 0.f, vdy = 0.f, vdz = 0.f;
    float nax = 0.f, nay = 0.f, naz = 0.f;
#pragma unroll
    for (int e = 0; e < 12; e++) {
        int c0 = E0[e], c1 = E1[e];
        float s0 = s[c0], s1 = s[c1];
        bool cr = ((s0 > 0.f) != (s1 > 0.f)) && surf;
        float wb = cr ? bn[e] : 0.f;
        wbe[e] = wb;
        wsum += wb;

        float w0 = an[c0] * fabsf(s0);
        float w1 = an[c1] * fabsf(s1);
        float invd = 1.f / (w0 + w1 + EPSF);
        float uex = (wx[c0] * w1 + wx[c1] * w0) * invd;
        float uey = (wy[c0] * w1 + wy[c1] * w0) * invd;
        float uez = (wz[c0] * w1 + wz[c1] * w0) * invd;
        vdx += uex * wb; vdy += uey * wb; vdz += uez * wb;

        float evx = wx[c1] - wx[c0];
        float evy = wy[c1] - wy[c0];
        float evz = wz[c1] - wz[c0];
        float elen = sqrtf(evx * evx + evy * evy + evz * evz) + EPSF;
        float ds = s1 - s0;
        float sg = (ds > 0.f) ? 1.f : ((ds < 0.f) ? -1.f : 0.f);
        float f = sg / elen * wb;
        nax += evx * f; nay += evy * f; naz += evz * f;
    }

    float invw = 1.f / (wsum + EPSF);
    vdx *= invw; vdy *= invw; vdz *= invw;
    nax *= invw; nay *= invw; naz *= invw;
    float nn = sqrtf(nax * nax + nay * nay + naz * naz) + EPSF;
    float innn = 1.f / nn;
    nax *= innn; nay *= innn; naz *= innn;

    // --- pass B: recompute ue, distances to vd ---
    float dist[12];
    float sumd = 0.f, ne = 0.f;
#pragma unroll
    for (int e = 0; e < 12; e++) {
        int c0 = E0[e], c1 = E1[e];
        float s0 = s[c0], s1 = s[c1];
        float cmf = (wbe[e] > 0.f) ? 1.f : 0.f;  // bn >= 0.01 always, so wbe>0 <=> cross
        float w0 = an[c0] * fabsf(s0);
        float w1 = an[c1] * fabsf(s1);
        float invd = 1.f / (w0 + w1 + EPSF);
        float dx = (wx[c0] * w1 + wx[c1] * w0) * invd - vdx;
        float dy = (wy[c0] * w1 + wy[c1] * w0) * invd - vdy;
        float dz = (wz[c0] * w1 + wz[c1] * w0) * invd - vdz;
        float d = sqrtf(dx * dx + dy * dy + dz * dz) * cmf;
        dist[e] = d;
        sumd += d;
        ne += cmf;
    }
    float mean = sumd / (ne + EPSF);

    // --- outputs ---
    float sm = surf ? 1.f : 0.f;
    size_t Ns = (size_t)N;
    float* vout = out;                 // vertices: 3N
    float* ldev = out + 3 * Ns;        // L_dev:   12N
    float* pout = out + 15 * Ns;       // p_alpha:  3N
    float* nout = out + 18 * Ns;       // n_out:    3N

    float vx = vdx * sm, vy = vdy * sm, vz = vdz * sm;
    vout[i * 3 + 0] = vx; vout[i * 3 + 1] = vy; vout[i * 3 + 2] = vz;
    pout[i * 3 + 0] = vx; pout[i * 3 + 1] = vy; pout[i * 3 + 2] = vz;
    nout[i * 3 + 0] = nax * sm; nout[i * 3 + 1] = nay * sm; nout[i * 3 + 2] = naz * sm;
#pragma unroll
    for (int e = 0; e < 12; e++) {
        float cmf = (wbe[e] > 0.f) ? 1.f : 0.f;
        ldev[(size_t)i * 12 + e] = fabsf(dist[e] - mean) * cmf;
    }
}

// ---------------------------------------------------------------------------
extern "C" void kernel_launch(void* const* d_in, const int* in_sizes, int n_in,
                              void* d_out, int out_size) {
    // metadata order: voxel_coords, sdf, cube_idx, resolution(scalar), deform,
    //                 beta, alpha, gamma
    int N = in_sizes[0] / 3;
    int M = in_sizes[1];
    // resolution may appear as a size-1 device input between cube_idx and deform
    int base = (n_in >= 8 && in_sizes[3] == 1) ? 4 : 3;

    const int*   vox    = (const int*)d_in[0];
    const float* sdf    = (const float*)d_in[1];
    const int*   cidx   = (const int*)d_in[2];      // int64 in numpy -> int32 on device
    const float* deform = (const float*)d_in[base + 0];
    const float* beta   = (const float*)d_in[base + 1];
    const float* alpha  = (const float*)d_in[base + 2];
    float* out = (float*)d_out;

    int total = N * 8;
    const float scale = 2.0f / 256.0f;   // resolution fixed at 256

    k_init   <<<(M + 255) / 256, 256>>>(M);
    k_scatter<<<(total + 255) / 256, 256>>>(cidx, total, M);
    k_world  <<<(M + 255) / 256, 256>>>(vox, deform, M, scale);
    k_main   <<<(N + 255) / 256, 256>>>(cidx, sdf, alpha, beta, out, N);
}

// round 4
// speedup vs baseline: 1.8868x; 1.8868x over previous
#include <cuda_runtime.h>
#include <cuda_bf16.h>

#define MAX_M 600000          // corners
#define EPSF 1e-8f
#define WSCALE 0.99f

// Scratch (no cudaMalloc allowed)
__device__ int    g_winner[MAX_M];     // last flat-index writer per corner slot
__device__ float4 g_ws[MAX_M];         // (world.x, world.y, world.z, sdf) per corner

// ---------------------------------------------------------------------------
// Kernel 0: init winners to -1
// ---------------------------------------------------------------------------
__global__ void k_init(int M) {
    int j = blockIdx.x * blockDim.x + threadIdx.x;
    if (j < M) g_winner[j] = -1;
}

// ---------------------------------------------------------------------------
// Kernel 1: winner = max flat index writing each slot (== JAX last-write-wins
// scatter). cube_idx arrives as int32. int4-vectorized: 4 atomics/thread.
// ---------------------------------------------------------------------------
__global__ void k_scatter(const int4* __restrict__ cube_idx, int total4, int M) {
    int t = blockIdx.x * blockDim.x + threadIdx.x;
    if (t >= total4) return;
    int4 v = cube_idx[t];
    int k = t * 4;
    int j;
    j = v.x; if (j < 0) j = 0; if (j >= M) j = M - 1; atomicMax(&g_winner[j], k + 0);
    j = v.y; if (j < 0) j = 0; if (j >= M) j = M - 1; atomicMax(&g_winner[j], k + 1);
    j = v.z; if (j < 0) j = 0; if (j >= M) j = M - 1; atomicMax(&g_winner[j], k + 2);
    j = v.w; if (j < 0) j = 0; if (j >= M) j = M - 1; atomicMax(&g_winner[j], k + 3);
}

// ---------------------------------------------------------------------------
// Kernel 2: g_ws[j] = (world.xyz, sdf[j]).
// world = unique_pos * (2/res) - 1 + deform,
// unique_pos[j] = voxel_coords[winner/8] + CUBE_CORNERS[winner&7] (or 0).
// ---------------------------------------------------------------------------
__global__ void k_world(const int* __restrict__ vox,
                        const float* __restrict__ deform,
                        const float* __restrict__ sdf,
                        int M, float scale) {
    int j = blockIdx.x * blockDim.x + threadIdx.x;
    if (j >= M) return;
    int k = g_winner[j];
    float px = 0.f, py = 0.f, pz = 0.f;
    if (k >= 0) {
        int i = k >> 3, c = k & 7;
        px = (float)vox[i * 3 + 0] + (float)(c & 1);
        py = (float)vox[i * 3 + 1] + (float)((c >> 1) & 1);
        pz = (float)vox[i * 3 + 2] + (float)((c >> 2) & 1);
    }
    float4 w;
    w.x = px * scale - 1.f + deform[j * 3 + 0];
    w.y = py * scale - 1.f + deform[j * 3 + 1];
    w.z = pz * scale - 1.f + deform[j * 3 + 2];
    w.w = sdf[j];
    g_ws[j] = w;
}

// ---------------------------------------------------------------------------
// Kernel 3: per-cube dual-contouring math. One thread per cube.
// Outputs (flat concat, float32): [vertices 3N][L_dev 12N][p_alpha 3N][n_out 3N]
// ---------------------------------------------------------------------------
__global__ void __launch_bounds__(256)
k_main(const int* __restrict__ cube_idx,
       const float* __restrict__ alpha,
       const float* __restrict__ beta,
       float* __restrict__ out, int N) {
    int i = blockIdx.x * blockDim.x + threadIdx.x;
    if (i >= N) return;

    // --- corner indices (coalesced int4 loads) ---
    const int4* cp = (const int4*)(cube_idx + (size_t)i * 8);
    int4 ca = cp[0], cb = cp[1];
    int ci[8] = {ca.x, ca.y, ca.z, ca.w, cb.x, cb.y, cb.z, cb.w};

    // --- one LDG.128 gather per corner: world.xyz + sdf ---
    float s[8], wx[8], wy[8], wz[8];
    bool anyp = false, anyn = false;
#pragma unroll
    for (int c = 0; c < 8; c++) {
        float4 w = __ldg(&g_ws[ci[c]]);
        wx[c] = w.x; wy[c] = w.y; wz[c] = w.z;
        s[c] = w.w;
        anyp |= (w.w > 0.f);
        anyn |= !(w.w > 0.f);
    }
    bool surf = anyp && anyn;

    // --- normalized weights ---
    const float4* ap = (const float4*)(alpha + (size_t)i * 8);
    float4 av0 = ap[0], av1 = ap[1];
    float aarr[8] = {av0.x, av0.y, av0.z, av0.w, av1.x, av1.y, av1.z, av1.w};
    float an[8];
#pragma unroll
    for (int c = 0; c < 8; c++) an[c] = tanhf(aarr[c]) * WSCALE + 1.f;

    float bn[12];
#pragma unroll
    for (int e = 0; e < 12; e++) bn[e] = tanhf(beta[(size_t)i * 12 + e]) * WSCALE + 1.f;

    const int E0[12] = {0, 1, 4, 0, 2, 3, 6, 2, 2, 3, 7, 6};
    const int E1[12] = {1, 5, 5, 4, 3, 7, 7, 6, 0, 1, 5, 4};

    // --- single pass: compute ue (kept in regs), wbe, vd / n_alpha accum ---
    float uex[12], uey[12], uez[12], wbe[12];
    float wsum = 0.f;
    float vdx = 0.f, vdy = 0.f, vdz = 0.f;
    float nax = 0.f, nay = 0.f, naz = 0.f;
#pragma unroll
    for (int e = 0; e < 12; e++) {
        int c0 = E0[e], c1 = E1[e];
        float s0 = s[c0], s1 = s[c1];
        bool cr = ((s0 > 0.f) != (s1 > 0.f)) && surf;
        float wb = cr ? bn[e] : 0.f;
        wbe[e] = wb;
        wsum += wb;

        float w0 = an[c0] * fabsf(s0);
        float w1 = an[c1] * fabsf(s1);
        float invd = 1.f / (w0 + w1 + EPSF);
        float ux = (wx[c0] * w1 + wx[c1] * w0) * invd;
        float uy = (wy[c0] * w1 + wy[c1] * w0) * invd;
        float uz = (wz[c0] * w1 + wz[c1] * w0) * invd;
        uex[e] = ux; uey[e] = uy; uez[e] = uz;
        vdx += ux * wb; vdy += uy * wb; vdz += uz * wb;

        float evx = wx[c1] - wx[c0];
        float evy = wy[c1] - wy[c0];
        float evz = wz[c1] - wz[c0];
        float elen = sqrtf(evx * evx + evy * evy + evz * evz) + EPSF;
        float ds = s1 - s0;
        float sg = (ds > 0.f) ? 1.f : ((ds < 0.f) ? -1.f : 0.f);
        float f = sg / elen * wb;
        nax += evx * f; nay += evy * f; naz += evz * f;
    }

    float invw = 1.f / (wsum + EPSF);
    vdx *= invw; vdy *= invw; vdz *= invw;
    nax *= invw; nay *= invw; naz *= invw;
    float nn = sqrtf(nax * nax + nay * nay + naz * naz) + EPSF;
    float innn = 1.f / nn;
    nax *= innn; nay *= innn; naz *= innn;

    // --- distances to vd (ue already in registers) ---
    float dist[12];
    float sumd = 0.f, ne = 0.f;
#pragma unroll
    for (int e = 0; e < 12; e++) {
        float cmf = (wbe[e] > 0.f) ? 1.f : 0.f;   // bn >= 0.01, so wbe>0 <=> cross
        float dx = uex[e] - vdx;
        float dy = uey[e] - vdy;
        float dz = uez[e] - vdz;
        float d = sqrtf(dx * dx + dy * dy + dz * dz) * cmf;
        dist[e] = d;
        sumd += d;
        ne += cmf;
    }
    float mean = sumd / (ne + EPSF);

    // --- outputs ---
    float sm = surf ? 1.f : 0.f;
    size_t Ns = (size_t)N;
    float* vout = out;                 // vertices: 3N
    float* ldev = out + 3 * Ns;        // L_dev:   12N
    float* pout = out + 15 * Ns;       // p_alpha:  3N
    float* nout = out + 18 * Ns;       // n_out:    3N

    float vx = vdx * sm, vy = vdy * sm, vz = vdz * sm;
    vout[i * 3 + 0] = vx; vout[i * 3 + 1] = vy; vout[i * 3 + 2] = vz;
    pout[i * 3 + 0] = vx; pout[i * 3 + 1] = vy; pout[i * 3 + 2] = vz;
    nout[i * 3 + 0] = nax * sm; nout[i * 3 + 1] = nay * sm; nout[i * 3 + 2] = naz * sm;
#pragma unroll
    for (int e = 0; e < 12; e++) {
        float cmf = (wbe[e] > 0.f) ? 1.f : 0.f;
        ldev[(size_t)i * 12 + e] = fabsf(dist[e] - mean) * cmf;
    }
}

// ---------------------------------------------------------------------------
extern "C" void kernel_launch(void* const* d_in, const int* in_sizes, int n_in,
                              void* d_out, int out_size) {
    int N = in_sizes[0] / 3;
    int M = in_sizes[1];
    int base = (n_in >= 8 && in_sizes[3] == 1) ? 4 : 3;

    const int*   vox    = (const int*)d_in[0];
    const float* sdf    = (const float*)d_in[1];
    const int*   cidx   = (const int*)d_in[2];
    const float* deform = (const float*)d_in[base + 0];
    const float* beta   = (const float*)d_in[base + 1];
    const float* alpha  = (const float*)d_in[base + 2];
    float* out = (float*)d_out;

    int total4 = N * 2;                  // N*8 indices / 4 per thread
    const float scale = 2.0f / 256.0f;

    k_init   <<<(M + 255) / 256, 256>>>(M);
    k_scatter<<<(total4 + 255) / 256, 256>>>((const int4*)cidx, total4, M);
    k_world  <<<(M + 255) / 256, 256>>>(vox, deform, sdf, M, scale);
    k_main   <<<(N + 255) / 256, 256>>>(cidx, alpha, beta, out, N);
}